// round 15
// baseline (speedup 1.0000x reference)
#include <cuda_runtime.h>
#include <cuda_fp16.h>
#include <cstdint>

#define N_NODES 50000
#define N_EDGES 1600000
#define N_GRAPHS 64

// ---------------- scratch (device globals; no allocations allowed) ----------
__device__ int   g_deg[N_NODES];
__device__ int   g_off[N_NODES + 1];
__device__ int   g_cursor[N_NODES];
__device__ float g_deginv[N_NODES];
__device__ int   g_srcs[N_EDGES];
__device__ int   g_partials[512];
__device__ int   g_gofs[N_GRAPHS + 1];

__device__ __half g_fA [(size_t)N_NODES * 256];   // feature ping (x, h2)
__device__ __half g_fB [(size_t)N_NODES * 256];   // feature pong (h1, P3)
__device__ __half g_a1h[(size_t)N_NODES * 256];   // aggregated features (fp16)
__device__ __half g_w1l[256 * 128], g_w1r[256 * 128];
__device__ __half g_w2l[256 * 256], g_w2r[256 * 256];
__device__ __half g_w3l[128 * 256], g_w3r[128 * 256];
__device__ float  g_h3 [(size_t)N_NODES * 128];   // Q3 then final h3 (fp32)

#define SCAN_CHUNK 128
#define N_CHUNKS ((N_NODES + SCAN_CHUNK - 1) / SCAN_CHUNK)   // 391

// ---------------- small asm helpers -----------------------------------------
__device__ __forceinline__ uint32_t smem_u32(const void* p) {
    uint32_t r;
    asm("{ .reg .u64 t; cvta.to.shared.u64 t, %1; cvt.u32.u64 %0, t; }" : "=r"(r) : "l"(p));
    return r;
}
__device__ __forceinline__ void cp_async16(uint32_t dst, const void* src, int src_bytes) {
    asm volatile("cp.async.cg.shared.global [%0], [%1], 16, %2;"
                 :: "r"(dst), "l"(src), "r"(src_bytes));
}
__device__ __forceinline__ void cp_commit() {
    asm volatile("cp.async.commit_group;" ::: "memory");
}
template <int NPend>
__device__ __forceinline__ void cp_wait() {
    asm volatile("cp.async.wait_group %0;" :: "n"(NPend) : "memory");
}
__device__ __forceinline__ void ldsm_x4(uint32_t addr, uint32_t& r0, uint32_t& r1,
                                        uint32_t& r2, uint32_t& r3) {
    asm volatile("ldmatrix.sync.aligned.m8n8.x4.shared.b16 {%0,%1,%2,%3}, [%4];"
                 : "=r"(r0), "=r"(r1), "=r"(r2), "=r"(r3) : "r"(addr));
}

// ---------------- fused setup: convert_x | zero_deg+gofs | convert_w | zero_out
__device__ __forceinline__ void cvt4(const float* src, __half* dst, int idx) {
    float4 v = ((const float4*)src)[idx];
    __half2 a = __floats2half2_rn(v.x, v.y);
    __half2 b = __floats2half2_rn(v.z, v.w);
    uint2 pk = { *(uint32_t*)&a, *(uint32_t*)&b };
    *(uint2*)(dst + (size_t)idx * 4) = pk;
}
#define SETUP_X   (N_NODES * 32)
#define SETUP_N   N_NODES
#define SETUP_W   32768
#define SETUP_O   (N_GRAPHS * 128)
#define SETUP_TOT (SETUP_X + SETUP_N + SETUP_W + SETUP_O)

__global__ void k_setup(const float* __restrict__ x, const int* __restrict__ batch,
                        const float* __restrict__ W1l, const float* __restrict__ W1r,
                        const float* __restrict__ W2l, const float* __restrict__ W2r,
                        const float* __restrict__ W3l, const float* __restrict__ W3r,
                        float* __restrict__ out) {
    int idx = blockIdx.x * blockDim.x + threadIdx.x;
    if (idx < SETUP_X) { cvt4(x, g_fA, idx); return; }
    idx -= SETUP_X;
    if (idx < SETUP_N) {
        int i = idx;
        g_deg[i] = 0;
        int b = batch[i];
        if (i == 0) {
            for (int g = 0; g <= b; ++g) g_gofs[g] = 0;
        } else {
            int p = batch[i - 1];
            if (p != b)
                for (int g = p + 1; g <= b; ++g) g_gofs[g] = i;
        }
        if (i == N_NODES - 1)
            for (int g = b + 1; g <= N_GRAPHS; ++g) g_gofs[g] = N_NODES;
        return;
    }
    idx -= SETUP_N;
    if (idx < SETUP_W) {
        const int S1 = 256 * 128 / 4;
        const int S2 = 256 * 256 / 4;
        if (idx < S1)              { cvt4(W1l, g_w1l, idx); cvt4(W1r, g_w1r, idx); return; }
        idx -= S1;
        if (idx < S2)              { cvt4(W2l, g_w2l, idx); cvt4(W2r, g_w2r, idx); return; }
        idx -= S2;
        { cvt4(W3l, g_w3l, idx); cvt4(W3r, g_w3r, idx); return; }
    }
    idx -= SETUP_W;
    if (idx < SETUP_O) out[idx] = 0.f;
}

// ---------------- preprocessing: counting sort of edges by dst --------------
__global__ void k_count(const int* __restrict__ ei) {
    int i = blockIdx.x * blockDim.x + threadIdx.x;
    if (i >= N_EDGES) return;
    atomicAdd(&g_deg[ei[N_EDGES + i]], 1);
}
__global__ void k_chunk_sums() {
    __shared__ int s[SCAN_CHUNK];
    int i = blockIdx.x * SCAN_CHUNK + threadIdx.x;
    s[threadIdx.x] = (i < N_NODES) ? g_deg[i] : 0;
    __syncthreads();
    for (int stride = SCAN_CHUNK / 2; stride > 0; stride >>= 1) {
        if (threadIdx.x < stride) s[threadIdx.x] += s[threadIdx.x + stride];
        __syncthreads();
    }
    if (threadIdx.x == 0) g_partials[blockIdx.x] = s[0];
}
__global__ void k_scan_partials() {
    __shared__ int s[512];
    int t = threadIdx.x;
    int v = (t < N_CHUNKS) ? g_partials[t] : 0;
    s[t] = v;
    __syncthreads();
    #pragma unroll
    for (int off = 1; off < 512; off <<= 1) {
        int x = (t >= off) ? s[t - off] : 0;
        __syncthreads();
        s[t] += x;
        __syncthreads();
    }
    if (t < N_CHUNKS) g_partials[t] = s[t] - v;   // exclusive
    if (t == 0) g_off[N_NODES] = N_EDGES;
}
__global__ void k_scan_chunks() {
    int i = blockIdx.x * SCAN_CHUNK + threadIdx.x;
    int d = (i < N_NODES) ? g_deg[i] : 0;
    int lane = threadIdx.x & 31, wid = threadIdx.x >> 5;
    __shared__ int ws[4];
    int x = d;
    #pragma unroll
    for (int off = 1; off < 32; off <<= 1) {
        int y = __shfl_up_sync(0xFFFFFFFFu, x, off);
        if (lane >= off) x += y;
    }
    if (lane == 31) ws[wid] = x;
    __syncthreads();
    int add = 0;
    #pragma unroll
    for (int w = 0; w < 4; ++w)
        if (w < wid) add += ws[w];
    int excl = x + add - d;
    if (i < N_NODES) {
        int o = g_partials[blockIdx.x] + excl;
        g_off[i] = o;
        g_cursor[i] = o;
        g_deginv[i] = (d > 0) ? (1.0f / (float)d) : 0.0f;
    }
}
__global__ void k_fill(const int* __restrict__ ei) {
    int i = blockIdx.x * blockDim.x + threadIdx.x;
    if (i >= N_EDGES) return;
    int s = ei[i];
    int d = ei[N_EDGES + i];
    int pos = atomicAdd(&g_cursor[d], 1);
    g_srcs[pos] = s;
}

// ---------------- aggregation: warp per node, fp16 gather, fp32 accum -------
template <int HV, int INSEL>
__device__ __forceinline__ void gather_node(int w, int lane, float2* accv) {
    const __half* base = (INSEL == 0) ? g_fA : g_fB;
    const int RV = HV * 32;
    int beg = g_off[w], end = g_off[w + 1];

    float2 acc0[HV], acc1[HV];
    #pragma unroll
    for (int v = 0; v < HV; ++v) {
        acc0[v] = make_float2(0.f, 0.f);
        acc1[v] = make_float2(0.f, 0.f);
    }
    int j = beg;
    for (; j + 2 <= end; j += 2) {
        int s0 = g_srcs[j], s1 = g_srcs[j + 1];
        const __half* p0 = base + ((size_t)s0 * RV + lane * HV) * 2;
        const __half* p1 = base + ((size_t)s1 * RV + lane * HV) * 2;
        __half2 h0[HV], h1[HV];
        if (HV == 4) {
            uint4 v0 = *(const uint4*)p0;
            uint4 v1 = *(const uint4*)p1;
            h0[0] = *(__half2*)&v0.x; h0[1] = *(__half2*)&v0.y;
            h0[2] = *(__half2*)&v0.z; h0[3] = *(__half2*)&v0.w;
            h1[0] = *(__half2*)&v1.x; h1[1] = *(__half2*)&v1.y;
            h1[2] = *(__half2*)&v1.z; h1[3] = *(__half2*)&v1.w;
        } else {
            uint2 v0 = *(const uint2*)p0;
            uint2 v1 = *(const uint2*)p1;
            h0[0] = *(__half2*)&v0.x; h0[1] = *(__half2*)&v0.y;
            h1[0] = *(__half2*)&v1.x; h1[1] = *(__half2*)&v1.y;
        }
        #pragma unroll
        for (int v = 0; v < HV; ++v) {
            float2 f0 = __half22float2(h0[v]);
            float2 f1 = __half22float2(h1[v]);
            acc0[v].x += f0.x; acc0[v].y += f0.y;
            acc1[v].x += f1.x; acc1[v].y += f1.y;
        }
    }
    if (j < end) {
        int s0 = g_srcs[j];
        const __half* p0 = base + ((size_t)s0 * RV + lane * HV) * 2;
        __half2 h0[HV];
        if (HV == 4) {
            uint4 v0 = *(const uint4*)p0;
            h0[0] = *(__half2*)&v0.x; h0[1] = *(__half2*)&v0.y;
            h0[2] = *(__half2*)&v0.z; h0[3] = *(__half2*)&v0.w;
        } else {
            uint2 v0 = *(const uint2*)p0;
            h0[0] = *(__half2*)&v0.x; h0[1] = *(__half2*)&v0.y;
        }
        #pragma unroll
        for (int v = 0; v < HV; ++v) {
            float2 f0 = __half22float2(h0[v]);
            acc0[v].x += f0.x; acc0[v].y += f0.y;
        }
    }
    #pragma unroll
    for (int v = 0; v < HV; ++v) {
        accv[v].x = acc0[v].x + acc1[v].x;
        accv[v].y = acc0[v].y + acc1[v].y;
    }
}

template <int HV, int INSEL>
__global__ void k_aggregate_f16() {
    int w = (blockIdx.x * blockDim.x + threadIdx.x) >> 5;
    if (w >= N_NODES) return;
    int lane = threadIdx.x & 31;
    float inv = g_deginv[w];
    float2 acc[HV];
    gather_node<HV, INSEL>(w, lane, acc);
    __half* row = g_a1h + (size_t)w * HV * 64;
    #pragma unroll
    for (int v = 0; v < HV; ++v) {
        __half2 r = __floats2half2_rn(acc[v].x * inv, acc[v].y * inv);
        *(__half2*)(row + (lane * HV + v) * 2) = r;
    }
}

// final L3 aggregation: gather P3 (g_fB, 128-d), h3 = relu(agg + Q3 + b3)
__global__ void k_agg_final(const float* __restrict__ bias) {
    int w = (blockIdx.x * blockDim.x + threadIdx.x) >> 5;
    if (w >= N_NODES) return;
    int lane = threadIdx.x & 31;
    float inv = g_deginv[w];
    float2 acc[2];
    gather_node<2, 1>(w, lane, acc);
    float* hrow = g_h3 + (size_t)w * 128;
    #pragma unroll
    for (int v = 0; v < 2; ++v) {
        int c = (lane * 2 + v) * 2;
        float2 q = *(float2*)(hrow + c);
        float2 b = *(const float2*)(bias + c);
        float2 o;
        o.x = fmaxf(acc[v].x * inv + q.x + b.x, 0.f);
        o.y = fmaxf(acc[v].y * inv + q.y + b.y, 0.f);
        *(float2*)(hrow + c) = o;
    }
}

// ---------------- fp16 HMMA GEMM (3-stage cp.async + ldmatrix) ---------------
__device__ __forceinline__ void mma16816h(float* c, const uint32_t* a, uint32_t b0, uint32_t b1) {
    asm volatile(
        "mma.sync.aligned.m16n8k16.row.col.f32.f16.f16.f32 "
        "{%0,%1,%2,%3}, {%4,%5,%6,%7}, {%8,%9}, {%0,%1,%2,%3};"
        : "+f"(c[0]), "+f"(c[1]), "+f"(c[2]), "+f"(c[3])
        : "r"(a[0]), "r"(a[1]), "r"(a[2]), "r"(a[3]), "r"(b0), "r"(b1));
}

#define GLD 40
#define TILEH (128 * GLD)
#define STAGES 3
#define GEMM_SMEM (STAGES * 2 * TILEH * 2)   // 61440 bytes

__device__ __forceinline__ void gemm_slab_load(
    const __half* __restrict__ Ap, const __half* __restrict__ Bp,
    int K, int koff, int bm, int bn, int t, int buf, __half* dynsm)
{
    __half* stage = dynsm + (size_t)buf * 2 * TILEH;
    __half* sA = stage;
    __half* sB = stage + TILEH;
    #pragma unroll
    for (int i = 0; i < 2; ++i) {
        int idx = t + i * 256;
        int row = idx >> 2, q = idx & 3;
        int gm = bm + row;
        int ok = (gm < N_NODES) ? 16 : 0;
        int gmc = (gm < N_NODES) ? gm : 0;
        cp_async16(smem_u32(sA + row * GLD + q * 8), Ap + (size_t)gmc * K + koff + q * 8, ok);
        cp_async16(smem_u32(sB + row * GLD + q * 8), Bp + (size_t)(bn + row) * K + koff + q * 8, 16);
    }
    cp_commit();
}

// ldmatrix-based mainloop: 6 LDSM per k16 (2 A, 4 B) feeding 16 HMMA
__device__ __forceinline__ void gemm_slab_mma(
    const __half* pA, const __half* pB, int wm, int wn, int lane,
    float acc[2][8][4])
{
    int la = lane & 15, ha = lane >> 4;
    int lb = lane & 7;
    int nb = (lane >> 4) & 1, kb = (lane >> 3) & 1;
    #pragma unroll
    for (int k16 = 0; k16 < 32; k16 += 16) {
        uint32_t a[2][4];
        #pragma unroll
        for (int i = 0; i < 2; ++i) {
            uint32_t addr = smem_u32(pA + (wm + i * 16 + la) * GLD + k16 + ha * 8);
            ldsm_x4(addr, a[i][0], a[i][1], a[i][2], a[i][3]);
        }
        #pragma unroll
        for (int jp = 0; jp < 4; ++jp) {
            uint32_t b0j, b1j, b0k, b1k;
            uint32_t addr = smem_u32(pB + (wn + jp * 16 + lb + nb * 8) * GLD + k16 + kb * 8);
            ldsm_x4(addr, b0j, b1j, b0k, b1k);
            #pragma unroll
            for (int i = 0; i < 2; ++i) mma16816h(acc[i][2 * jp],     a[i], b0j, b1j);
            #pragma unroll
            for (int i = 0; i < 2; ++i) mma16816h(acc[i][2 * jp + 1], a[i], b0k, b1k);
        }
    }
}

// dual-A GEMM + bias + relu. WSEL: 1 -> (w1l,w1r), 2 -> (w2l,w2r)
template <int K, int N, int WSEL, int INSEL, int OUTSEL>
__global__ __launch_bounds__(256, 2)
void k_gemm_dual(const float* __restrict__ bias) {
    extern __shared__ __half dynsm[];
    const __half* __restrict__ A1 = g_a1h;
    const __half* __restrict__ A2 = (INSEL == 0) ? g_fA : g_fB;
    const __half* __restrict__ Bl = (WSEL == 1) ? g_w1l : g_w2l;
    const __half* __restrict__ Br = (WSEL == 1) ? g_w1r : g_w2r;

    int t = threadIdx.x;
    int lane = t & 31, wid = t >> 5;
    int wm = (wid & 3) * 32, wn = (wid >> 2) * 64;
    int bm = blockIdx.x * 128, bn = blockIdx.y * 128;
    int g = lane >> 2, tq = lane & 3;

    float acc[2][8][4];
    #pragma unroll
    for (int i = 0; i < 2; ++i)
        #pragma unroll
        for (int j = 0; j < 8; ++j)
            #pragma unroll
            for (int q = 0; q < 4; ++q) acc[i][j][q] = 0.f;

    constexpr int HALF = K / 32;
    constexpr int SLABS = 2 * HALF;

    auto srcA = [&](int s) { return (s < HALF) ? A1 : A2; };
    auto srcB = [&](int s) { return (s < HALF) ? Bl : Br; };
    auto koff = [&](int s) { return ((s < HALF) ? s : s - HALF) * 32; };

    gemm_slab_load(srcA(0), srcB(0), K, koff(0), bm, bn, t, 0, dynsm);
    gemm_slab_load(srcA(1), srcB(1), K, koff(1), bm, bn, t, 1, dynsm);
    for (int s = 0; s < SLABS; ++s) {
        cp_wait<1>();
        __syncthreads();
        if (s + 2 < SLABS)
            gemm_slab_load(srcA(s + 2), srcB(s + 2), K, koff(s + 2), bm, bn, t, (s + 2) % STAGES, dynsm);
        else
            cp_commit();
        const __half* pA = dynsm + (size_t)(s % STAGES) * 2 * TILEH;
        gemm_slab_mma(pA, pA + TILEH, wm, wn, lane, acc);
    }

    #pragma unroll
    for (int i = 0; i < 2; ++i) {
        int rows[2] = { bm + wm + i * 16 + g, bm + wm + i * 16 + g + 8 };
        #pragma unroll
        for (int j = 0; j < 8; ++j) {
            int col = bn + wn + j * 8 + 2 * tq;
            float b0 = __ldg(bias + col), b1 = __ldg(bias + col + 1);
            #pragma unroll
            for (int h = 0; h < 2; ++h) {
                int row = rows[h];
                if (row >= N_NODES) continue;
                float ox = fmaxf(acc[i][j][h * 2 + 0] + b0, 0.f);
                float oy = fmaxf(acc[i][j][h * 2 + 1] + b1, 0.f);
                __half* outp = (OUTSEL == 0) ? g_fB : g_fA;
                __half2 hh = __floats2half2_rn(ox, oy);
                *(__half2*)(outp + (size_t)row * N + col) = hh;
            }
        }
    }
}

// single-A GEMM for L3: A = g_fA (h2, K=256)
__global__ __launch_bounds__(256, 2)
void k_gemm_l3() {
    extern __shared__ __half dynsm[];
    constexpr int K = 256, N = 128;
    const __half* __restrict__ A = g_fA;
    const __half* __restrict__ B = (blockIdx.y == 0) ? g_w3l : g_w3r;

    int t = threadIdx.x;
    int lane = t & 31, wid = t >> 5;
    int wm = (wid & 3) * 32, wn = (wid >> 2) * 64;
    int bm = blockIdx.x * 128;
    int g = lane >> 2, tq = lane & 3;

    float acc[2][8][4];
    #pragma unroll
    for (int i = 0; i < 2; ++i)
        #pragma unroll
        for (int j = 0; j < 8; ++j)
            #pragma unroll
            for (int q = 0; q < 4; ++q) acc[i][j][q] = 0.f;

    constexpr int SLABS = K / 32;
    gemm_slab_load(A, B, K, 0, bm, 0, t, 0, dynsm);
    gemm_slab_load(A, B, K, 32, bm, 0, t, 1, dynsm);
    for (int s = 0; s < SLABS; ++s) {
        cp_wait<1>();
        __syncthreads();
        if (s + 2 < SLABS)
            gemm_slab_load(A, B, K, (s + 2) * 32, bm, 0, t, (s + 2) % STAGES, dynsm);
        else
            cp_commit();
        const __half* pA = dynsm + (size_t)(s % STAGES) * 2 * TILEH;
        gemm_slab_mma(pA, pA + TILEH, wm, wn, lane, acc);
    }

    bool q3 = (blockIdx.y == 1);
    #pragma unroll
    for (int i = 0; i < 2; ++i) {
        int rows[2] = { bm + wm + i * 16 + g, bm + wm + i * 16 + g + 8 };
        #pragma unroll
        for (int j = 0; j < 8; ++j) {
            int col = wn + j * 8 + 2 * tq;
            #pragma unroll
            for (int h = 0; h < 2; ++h) {
                int row = rows[h];
                if (row >= N_NODES) continue;
                float ox = acc[i][j][h * 2 + 0];
                float oy = acc[i][j][h * 2 + 1];
                if (q3) {
                    float2 o = { ox, oy };
                    *(float2*)(g_h3 + (size_t)row * N + col) = o;
                } else {
                    __half2 hh = __floats2half2_rn(ox, oy);
                    *(__half2*)(g_fB + (size_t)row * N + col) = hh;
                }
            }
        }
    }
}

// ---------------- global add pool (segment-based, batch sorted) --------------
#define POOL_SPLIT 8
__global__ void k_pool_seg(float* __restrict__ out) {
    int gph = blockIdx.x;
    int part = blockIdx.y;
    int c = threadIdx.x;
    int beg = g_gofs[gph], end = g_gofs[gph + 1];
    float s = 0.f;
    for (int i = beg + part; i < end; i += POOL_SPLIT)
        s += g_h3[(size_t)i * 128 + c];
    atomicAdd(&out[gph * 128 + c], s);
}

// ---------------- launch ----------------------------------------------------
extern "C" void kernel_launch(void* const* d_in, const int* in_sizes, int n_in,
                              void* d_out, int out_size) {
    const float* x     = (const float*)d_in[0];
    const int*   ei    = (const int*)d_in[1];
    const int*   batch = (const int*)d_in[2];
    const float* W1l = (const float*)d_in[3];
    const float* b1  = (const float*)d_in[4];
    const float* W1r = (const float*)d_in[5];
    const float* W2l = (const float*)d_in[6];
    const float* b2  = (const float*)d_in[7];
    const float* W2r = (const float*)d_in[8];
    const float* W3l = (const float*)d_in[9];
    const float* b3  = (const float*)d_in[10];
    const float* W3r = (const float*)d_in[11];
    float* out = (float*)d_out;

    const int EB   = (N_EDGES + 255) / 256;
    const int AGGB = (N_NODES * 32 + 255) / 256;

    cudaFuncSetAttribute(k_gemm_dual<128, 256, 1, 0, 0>, cudaFuncAttributeMaxDynamicSharedMemorySize, GEMM_SMEM);
    cudaFuncSetAttribute(k_gemm_dual<256, 256, 2, 1, 1>, cudaFuncAttributeMaxDynamicSharedMemorySize, GEMM_SMEM);
    cudaFuncSetAttribute(k_gemm_l3, cudaFuncAttributeMaxDynamicSharedMemorySize, GEMM_SMEM);

    // fused setup + preprocessing
    k_setup<<<(SETUP_TOT + 255) / 256, 256>>>(x, batch, W1l, W1r, W2l, W2r, W3l, W3r, out);
    k_count<<<EB, 256>>>(ei);
    k_chunk_sums<<<N_CHUNKS, SCAN_CHUNK>>>();
    k_scan_partials<<<1, 512>>>();
    k_scan_chunks<<<N_CHUNKS, SCAN_CHUNK>>>();
    k_fill<<<EB, 256>>>(ei);

    dim3 gm1((N_NODES + 127) / 128, 2);   // N=256
    dim3 gm3((N_NODES + 127) / 128, 2);   // L3: y -> {P3, Q3}

    // layer 1: K=128 -> 256   (in g_fA, out g_fB)
    k_aggregate_f16<2, 0><<<AGGB, 256>>>();
    k_gemm_dual<128, 256, 1, 0, 0><<<gm1, 256, GEMM_SMEM>>>(b1);
    // layer 2: K=256 -> 256   (in g_fB, out g_fA)
    k_aggregate_f16<4, 1><<<AGGB, 256>>>();
    k_gemm_dual<256, 256, 2, 1, 1><<<gm1, 256, GEMM_SMEM>>>(b2);
    // layer 3: P3/Q3 GEMM first, then gather P3 (128-d)
    k_gemm_l3<<<gm3, 256, GEMM_SMEM>>>();
    k_agg_final<<<AGGB, 256>>>(b3);

    // global add pool (out zeroed in k_setup)
    dim3 pg(N_GRAPHS, POOL_SPLIT);
    k_pool_seg<<<pg, 128>>>(out);
}

// round 16
// speedup vs baseline: 1.0367x; 1.0367x over previous
#include <cuda_runtime.h>
#include <cuda_fp16.h>
#include <cstdint>

#define N_NODES 50000
#define N_EDGES 1600000
#define N_GRAPHS 64

// ---------------- scratch (device globals; no allocations allowed) ----------
__device__ int   g_deg[N_NODES];
__device__ int   g_off[N_NODES + 1];
__device__ int   g_cursor[N_NODES];
__device__ float g_deginv[N_NODES];
__device__ int   g_srcs[N_EDGES];
__device__ int   g_partials[512];
__device__ int   g_gofs[N_GRAPHS + 1];

__device__ __half g_fA [(size_t)N_NODES * 256];   // feature ping (x, h2)
__device__ __half g_fB [(size_t)N_NODES * 256];   // feature pong (h1, P3)
__device__ __half g_a1h[(size_t)N_NODES * 256];   // aggregated features (fp16)
__device__ __half g_w1l[256 * 128], g_w1r[256 * 128];
__device__ __half g_w2l[256 * 256], g_w2r[256 * 256];
__device__ __half g_w3l[128 * 256], g_w3r[128 * 256];
__device__ float  g_h3 [(size_t)N_NODES * 128];   // Q3 then final h3 (fp32)

#define SCAN_CHUNK 128
#define N_CHUNKS ((N_NODES + SCAN_CHUNK - 1) / SCAN_CHUNK)   // 391

// ---------------- small asm helpers -----------------------------------------
__device__ __forceinline__ uint32_t smem_u32(const void* p) {
    uint32_t r;
    asm("{ .reg .u64 t; cvta.to.shared.u64 t, %1; cvt.u32.u64 %0, t; }" : "=r"(r) : "l"(p));
    return r;
}
__device__ __forceinline__ void cp_async16(uint32_t dst, const void* src, int src_bytes) {
    asm volatile("cp.async.cg.shared.global [%0], [%1], 16, %2;"
                 :: "r"(dst), "l"(src), "r"(src_bytes));
}
__device__ __forceinline__ void cp_commit() {
    asm volatile("cp.async.commit_group;" ::: "memory");
}
template <int NPend>
__device__ __forceinline__ void cp_wait() {
    asm volatile("cp.async.wait_group %0;" :: "n"(NPend) : "memory");
}
__device__ __forceinline__ void ldsm_x4(uint32_t addr, uint32_t& r0, uint32_t& r1,
                                        uint32_t& r2, uint32_t& r3) {
    asm volatile("ldmatrix.sync.aligned.m8n8.x4.shared.b16 {%0,%1,%2,%3}, [%4];"
                 : "=r"(r0), "=r"(r1), "=r"(r2), "=r"(r3) : "r"(addr));
}

// ---------------- setup (side branch): convert_x | gofs | convert_w | zero_out
__device__ __forceinline__ void cvt4(const float* src, __half* dst, int idx) {
    float4 v = ((const float4*)src)[idx];
    __half2 a = __floats2half2_rn(v.x, v.y);
    __half2 b = __floats2half2_rn(v.z, v.w);
    uint2 pk = { *(uint32_t*)&a, *(uint32_t*)&b };
    *(uint2*)(dst + (size_t)idx * 4) = pk;
}
#define SETUP_X   (N_NODES * 32)
#define SETUP_N   N_NODES
#define SETUP_W   32768
#define SETUP_O   (N_GRAPHS * 128)
#define SETUP_TOT (SETUP_X + SETUP_N + SETUP_W + SETUP_O)

__global__ void k_setup(const float* __restrict__ x, const int* __restrict__ batch,
                        const float* __restrict__ W1l, const float* __restrict__ W1r,
                        const float* __restrict__ W2l, const float* __restrict__ W2r,
                        const float* __restrict__ W3l, const float* __restrict__ W3r,
                        float* __restrict__ out) {
    int idx = blockIdx.x * blockDim.x + threadIdx.x;
    if (idx < SETUP_X) { cvt4(x, g_fA, idx); return; }
    idx -= SETUP_X;
    if (idx < SETUP_N) {
        int i = idx;
        int b = batch[i];
        if (i == 0) {
            for (int g = 0; g <= b; ++g) g_gofs[g] = 0;
        } else {
            int p = batch[i - 1];
            if (p != b)
                for (int g = p + 1; g <= b; ++g) g_gofs[g] = i;
        }
        if (i == N_NODES - 1)
            for (int g = b + 1; g <= N_GRAPHS; ++g) g_gofs[g] = N_NODES;
        return;
    }
    idx -= SETUP_N;
    if (idx < SETUP_W) {
        const int S1 = 256 * 128 / 4;
        const int S2 = 256 * 256 / 4;
        if (idx < S1)              { cvt4(W1l, g_w1l, idx); cvt4(W1r, g_w1r, idx); return; }
        idx -= S1;
        if (idx < S2)              { cvt4(W2l, g_w2l, idx); cvt4(W2r, g_w2r, idx); return; }
        idx -= S2;
        { cvt4(W3l, g_w3l, idx); cvt4(W3r, g_w3r, idx); return; }
    }
    idx -= SETUP_W;
    if (idx < SETUP_O) out[idx] = 0.f;
}

// ---------------- preprocessing (main branch): counting sort by dst ---------
__global__ void k_zero_deg() {
    int i = blockIdx.x * blockDim.x + threadIdx.x;
    if (i < N_NODES) g_deg[i] = 0;
}
__global__ void k_count(const int* __restrict__ ei) {
    int i = blockIdx.x * blockDim.x + threadIdx.x;
    if (i >= N_EDGES) return;
    atomicAdd(&g_deg[ei[N_EDGES + i]], 1);
}
__global__ void k_chunk_sums() {
    __shared__ int s[SCAN_CHUNK];
    int i = blockIdx.x * SCAN_CHUNK + threadIdx.x;
    s[threadIdx.x] = (i < N_NODES) ? g_deg[i] : 0;
    __syncthreads();
    for (int stride = SCAN_CHUNK / 2; stride > 0; stride >>= 1) {
        if (threadIdx.x < stride) s[threadIdx.x] += s[threadIdx.x + stride];
        __syncthreads();
    }
    if (threadIdx.x == 0) g_partials[blockIdx.x] = s[0];
}
__global__ void k_scan_partials() {
    __shared__ int s[512];
    int t = threadIdx.x;
    int v = (t < N_CHUNKS) ? g_partials[t] : 0;
    s[t] = v;
    __syncthreads();
    #pragma unroll
    for (int off = 1; off < 512; off <<= 1) {
        int x = (t >= off) ? s[t - off] : 0;
        __syncthreads();
        s[t] += x;
        __syncthreads();
    }
    if (t < N_CHUNKS) g_partials[t] = s[t] - v;   // exclusive
    if (t == 0) g_off[N_NODES] = N_EDGES;
}
__global__ void k_scan_chunks() {
    int i = blockIdx.x * SCAN_CHUNK + threadIdx.x;
    int d = (i < N_NODES) ? g_deg[i] : 0;
    int lane = threadIdx.x & 31, wid = threadIdx.x >> 5;
    __shared__ int ws[4];
    int x = d;
    #pragma unroll
    for (int off = 1; off < 32; off <<= 1) {
        int y = __shfl_up_sync(0xFFFFFFFFu, x, off);
        if (lane >= off) x += y;
    }
    if (lane == 31) ws[wid] = x;
    __syncthreads();
    int add = 0;
    #pragma unroll
    for (int w = 0; w < 4; ++w)
        if (w < wid) add += ws[w];
    int excl = x + add - d;
    if (i < N_NODES) {
        int o = g_partials[blockIdx.x] + excl;
        g_off[i] = o;
        g_cursor[i] = o;
        g_deginv[i] = (d > 0) ? (1.0f / (float)d) : 0.0f;
    }
}
__global__ void k_fill(const int* __restrict__ ei) {
    int i = blockIdx.x * blockDim.x + threadIdx.x;
    if (i >= N_EDGES) return;
    int s = ei[i];
    int d = ei[N_EDGES + i];
    int pos = atomicAdd(&g_cursor[d], 1);
    g_srcs[pos] = s;
}

// ---------------- aggregation: warp per node, fp16 gather, fp32 accum -------
template <int HV, int INSEL>
__device__ __forceinline__ void gather_node(int w, int lane, float2* accv) {
    const __half* base = (INSEL == 0) ? g_fA : g_fB;
    const int RV = HV * 32;
    int beg = g_off[w], end = g_off[w + 1];

    float2 acc0[HV], acc1[HV];
    #pragma unroll
    for (int v = 0; v < HV; ++v) {
        acc0[v] = make_float2(0.f, 0.f);
        acc1[v] = make_float2(0.f, 0.f);
    }
    int j = beg;
    for (; j + 2 <= end; j += 2) {
        int s0 = g_srcs[j], s1 = g_srcs[j + 1];
        const __half* p0 = base + ((size_t)s0 * RV + lane * HV) * 2;
        const __half* p1 = base + ((size_t)s1 * RV + lane * HV) * 2;
        __half2 h0[HV], h1[HV];
        if (HV == 4) {
            uint4 v0 = *(const uint4*)p0;
            uint4 v1 = *(const uint4*)p1;
            h0[0] = *(__half2*)&v0.x; h0[1] = *(__half2*)&v0.y;
            h0[2] = *(__half2*)&v0.z; h0[3] = *(__half2*)&v0.w;
            h1[0] = *(__half2*)&v1.x; h1[1] = *(__half2*)&v1.y;
            h1[2] = *(__half2*)&v1.z; h1[3] = *(__half2*)&v1.w;
        } else {
            uint2 v0 = *(const uint2*)p0;
            uint2 v1 = *(const uint2*)p1;
            h0[0] = *(__half2*)&v0.x; h0[1] = *(__half2*)&v0.y;
            h1[0] = *(__half2*)&v1.x; h1[1] = *(__half2*)&v1.y;
        }
        #pragma unroll
        for (int v = 0; v < HV; ++v) {
            float2 f0 = __half22float2(h0[v]);
            float2 f1 = __half22float2(h1[v]);
            acc0[v].x += f0.x; acc0[v].y += f0.y;
            acc1[v].x += f1.x; acc1[v].y += f1.y;
        }
    }
    if (j < end) {
        int s0 = g_srcs[j];
        const __half* p0 = base + ((size_t)s0 * RV + lane * HV) * 2;
        __half2 h0[HV];
        if (HV == 4) {
            uint4 v0 = *(const uint4*)p0;
            h0[0] = *(__half2*)&v0.x; h0[1] = *(__half2*)&v0.y;
            h0[2] = *(__half2*)&v0.z; h0[3] = *(__half2*)&v0.w;
        } else {
            uint2 v0 = *(const uint2*)p0;
            h0[0] = *(__half2*)&v0.x; h0[1] = *(__half2*)&v0.y;
        }
        #pragma unroll
        for (int v = 0; v < HV; ++v) {
            float2 f0 = __half22float2(h0[v]);
            acc0[v].x += f0.x; acc0[v].y += f0.y;
        }
    }
    #pragma unroll
    for (int v = 0; v < HV; ++v) {
        accv[v].x = acc0[v].x + acc1[v].x;
        accv[v].y = acc0[v].y + acc1[v].y;
    }
}

template <int HV, int INSEL>
__global__ void k_aggregate_f16() {
    int w = (blockIdx.x * blockDim.x + threadIdx.x) >> 5;
    if (w >= N_NODES) return;
    int lane = threadIdx.x & 31;
    float inv = g_deginv[w];
    float2 acc[HV];
    gather_node<HV, INSEL>(w, lane, acc);
    __half* row = g_a1h + (size_t)w * HV * 64;
    #pragma unroll
    for (int v = 0; v < HV; ++v) {
        __half2 r = __floats2half2_rn(acc[v].x * inv, acc[v].y * inv);
        *(__half2*)(row + (lane * HV + v) * 2) = r;
    }
}

// final L3 aggregation: gather P3 (g_fB, 128-d), h3 = relu(agg + Q3 + b3)
__global__ void k_agg_final(const float* __restrict__ bias) {
    int w = (blockIdx.x * blockDim.x + threadIdx.x) >> 5;
    if (w >= N_NODES) return;
    int lane = threadIdx.x & 31;
    float inv = g_deginv[w];
    float2 acc[2];
    gather_node<2, 1>(w, lane, acc);
    float* hrow = g_h3 + (size_t)w * 128;
    #pragma unroll
    for (int v = 0; v < 2; ++v) {
        int c = (lane * 2 + v) * 2;
        float2 q = *(float2*)(hrow + c);
        float2 b = *(const float2*)(bias + c);
        float2 o;
        o.x = fmaxf(acc[v].x * inv + q.x + b.x, 0.f);
        o.y = fmaxf(acc[v].y * inv + q.y + b.y, 0.f);
        *(float2*)(hrow + c) = o;
    }
}

// ---------------- fp16 HMMA GEMM (3-stage cp.async + ldmatrix) ---------------
__device__ __forceinline__ void mma16816h(float* c, const uint32_t* a, uint32_t b0, uint32_t b1) {
    asm volatile(
        "mma.sync.aligned.m16n8k16.row.col.f32.f16.f16.f32 "
        "{%0,%1,%2,%3}, {%4,%5,%6,%7}, {%8,%9}, {%0,%1,%2,%3};"
        : "+f"(c[0]), "+f"(c[1]), "+f"(c[2]), "+f"(c[3])
        : "r"(a[0]), "r"(a[1]), "r"(a[2]), "r"(a[3]), "r"(b0), "r"(b1));
}

#define GLD 40
#define TILEH (128 * GLD)
#define STAGES 3
#define GEMM_SMEM (STAGES * 2 * TILEH * 2)   // 61440 bytes

__device__ __forceinline__ void gemm_slab_load(
    const __half* __restrict__ Ap, const __half* __restrict__ Bp,
    int K, int koff, int bm, int bn, int t, int buf, __half* dynsm)
{
    __half* stage = dynsm + (size_t)buf * 2 * TILEH;
    __half* sA = stage;
    __half* sB = stage + TILEH;
    #pragma unroll
    for (int i = 0; i < 2; ++i) {
        int idx = t + i * 256;
        int row = idx >> 2, q = idx & 3;
        int gm = bm + row;
        int ok = (gm < N_NODES) ? 16 : 0;
        int gmc = (gm < N_NODES) ? gm : 0;
        cp_async16(smem_u32(sA + row * GLD + q * 8), Ap + (size_t)gmc * K + koff + q * 8, ok);
        cp_async16(smem_u32(sB + row * GLD + q * 8), Bp + (size_t)(bn + row) * K + koff + q * 8, 16);
    }
    cp_commit();
}

// ldmatrix-based mainloop: 6 LDSM per k16 (2 A, 4 B) feeding 16 HMMA
__device__ __forceinline__ void gemm_slab_mma(
    const __half* pA, const __half* pB, int wm, int wn, int lane,
    float acc[2][8][4])
{
    int la = lane & 15, ha = lane >> 4;
    int lb = lane & 7;
    int nb = (lane >> 4) & 1, kb = (lane >> 3) & 1;
    #pragma unroll
    for (int k16 = 0; k16 < 32; k16 += 16) {
        uint32_t a[2][4];
        #pragma unroll
        for (int i = 0; i < 2; ++i) {
            uint32_t addr = smem_u32(pA + (wm + i * 16 + la) * GLD + k16 + ha * 8);
            ldsm_x4(addr, a[i][0], a[i][1], a[i][2], a[i][3]);
        }
        #pragma unroll
        for (int jp = 0; jp < 4; ++jp) {
            uint32_t b0j, b1j, b0k, b1k;
            uint32_t addr = smem_u32(pB + (wn + jp * 16 + lb + nb * 8) * GLD + k16 + kb * 8);
            ldsm_x4(addr, b0j, b1j, b0k, b1k);
            #pragma unroll
            for (int i = 0; i < 2; ++i) mma16816h(acc[i][2 * jp],     a[i], b0j, b1j);
            #pragma unroll
            for (int i = 0; i < 2; ++i) mma16816h(acc[i][2 * jp + 1], a[i], b0k, b1k);
        }
    }
}

// dual-A GEMM + bias + relu. WSEL: 1 -> (w1l,w1r), 2 -> (w2l,w2r)
template <int K, int N, int WSEL, int INSEL, int OUTSEL>
__global__ __launch_bounds__(256, 2)
void k_gemm_dual(const float* __restrict__ bias) {
    extern __shared__ __half dynsm[];
    const __half* __restrict__ A1 = g_a1h;
    const __half* __restrict__ A2 = (INSEL == 0) ? g_fA : g_fB;
    const __half* __restrict__ Bl = (WSEL == 1) ? g_w1l : g_w2l;
    const __half* __restrict__ Br = (WSEL == 1) ? g_w1r : g_w2r;

    int t = threadIdx.x;
    int lane = t & 31, wid = t >> 5;
    int wm = (wid & 3) * 32, wn = (wid >> 2) * 64;
    int bm = blockIdx.x * 128, bn = blockIdx.y * 128;
    int g = lane >> 2, tq = lane & 3;

    float acc[2][8][4];
    #pragma unroll
    for (int i = 0; i < 2; ++i)
        #pragma unroll
        for (int j = 0; j < 8; ++j)
            #pragma unroll
            for (int q = 0; q < 4; ++q) acc[i][j][q] = 0.f;

    constexpr int HALF = K / 32;
    constexpr int SLABS = 2 * HALF;

    auto srcA = [&](int s) { return (s < HALF) ? A1 : A2; };
    auto srcB = [&](int s) { return (s < HALF) ? Bl : Br; };
    auto koff = [&](int s) { return ((s < HALF) ? s : s - HALF) * 32; };

    gemm_slab_load(srcA(0), srcB(0), K, koff(0), bm, bn, t, 0, dynsm);
    gemm_slab_load(srcA(1), srcB(1), K, koff(1), bm, bn, t, 1, dynsm);
    for (int s = 0; s < SLABS; ++s) {
        cp_wait<1>();
        __syncthreads();
        if (s + 2 < SLABS)
            gemm_slab_load(srcA(s + 2), srcB(s + 2), K, koff(s + 2), bm, bn, t, (s + 2) % STAGES, dynsm);
        else
            cp_commit();
        const __half* pA = dynsm + (size_t)(s % STAGES) * 2 * TILEH;
        gemm_slab_mma(pA, pA + TILEH, wm, wn, lane, acc);
    }

    #pragma unroll
    for (int i = 0; i < 2; ++i) {
        int rows[2] = { bm + wm + i * 16 + g, bm + wm + i * 16 + g + 8 };
        #pragma unroll
        for (int j = 0; j < 8; ++j) {
            int col = bn + wn + j * 8 + 2 * tq;
            float b0 = __ldg(bias + col), b1 = __ldg(bias + col + 1);
            #pragma unroll
            for (int h = 0; h < 2; ++h) {
                int row = rows[h];
                if (row >= N_NODES) continue;
                float ox = fmaxf(acc[i][j][h * 2 + 0] + b0, 0.f);
                float oy = fmaxf(acc[i][j][h * 2 + 1] + b1, 0.f);
                __half* outp = (OUTSEL == 0) ? g_fB : g_fA;
                __half2 hh = __floats2half2_rn(ox, oy);
                *(__half2*)(outp + (size_t)row * N + col) = hh;
            }
        }
    }
}

// single-A GEMM for L3: A = g_fA (h2, K=256)
__global__ __launch_bounds__(256, 2)
void k_gemm_l3() {
    extern __shared__ __half dynsm[];
    constexpr int K = 256, N = 128;
    const __half* __restrict__ A = g_fA;
    const __half* __restrict__ B = (blockIdx.y == 0) ? g_w3l : g_w3r;

    int t = threadIdx.x;
    int lane = t & 31, wid = t >> 5;
    int wm = (wid & 3) * 32, wn = (wid >> 2) * 64;
    int bm = blockIdx.x * 128;
    int g = lane >> 2, tq = lane & 3;

    float acc[2][8][4];
    #pragma unroll
    for (int i = 0; i < 2; ++i)
        #pragma unroll
        for (int j = 0; j < 8; ++j)
            #pragma unroll
            for (int q = 0; q < 4; ++q) acc[i][j][q] = 0.f;

    constexpr int SLABS = K / 32;
    gemm_slab_load(A, B, K, 0, bm, 0, t, 0, dynsm);
    gemm_slab_load(A, B, K, 32, bm, 0, t, 1, dynsm);
    for (int s = 0; s < SLABS; ++s) {
        cp_wait<1>();
        __syncthreads();
        if (s + 2 < SLABS)
            gemm_slab_load(A, B, K, (s + 2) * 32, bm, 0, t, (s + 2) % STAGES, dynsm);
        else
            cp_commit();
        const __half* pA = dynsm + (size_t)(s % STAGES) * 2 * TILEH;
        gemm_slab_mma(pA, pA + TILEH, wm, wn, lane, acc);
    }

    bool q3 = (blockIdx.y == 1);
    #pragma unroll
    for (int i = 0; i < 2; ++i) {
        int rows[2] = { bm + wm + i * 16 + g, bm + wm + i * 16 + g + 8 };
        #pragma unroll
        for (int j = 0; j < 8; ++j) {
            int col = wn + j * 8 + 2 * tq;
            #pragma unroll
            for (int h = 0; h < 2; ++h) {
                int row = rows[h];
                if (row >= N_NODES) continue;
                float ox = acc[i][j][h * 2 + 0];
                float oy = acc[i][j][h * 2 + 1];
                if (q3) {
                    float2 o = { ox, oy };
                    *(float2*)(g_h3 + (size_t)row * N + col) = o;
                } else {
                    __half2 hh = __floats2half2_rn(ox, oy);
                    *(__half2*)(g_fB + (size_t)row * N + col) = hh;
                }
            }
        }
    }
}

// ---------------- global add pool (segment-based, batch sorted) --------------
#define POOL_SPLIT 8
__global__ void k_pool_seg(float* __restrict__ out) {
    int gph = blockIdx.x;
    int part = blockIdx.y;
    int c = threadIdx.x;
    int beg = g_gofs[gph], end = g_gofs[gph + 1];
    float s = 0.f;
    for (int i = beg + part; i < end; i += POOL_SPLIT)
        s += g_h3[(size_t)i * 128 + c];
    atomicAdd(&out[gph * 128 + c], s);
}

// ---------------- launch: setup forked against edge preprocessing ------------
extern "C" void kernel_launch(void* const* d_in, const int* in_sizes, int n_in,
                              void* d_out, int out_size) {
    const float* x     = (const float*)d_in[0];
    const int*   ei    = (const int*)d_in[1];
    const int*   batch = (const int*)d_in[2];
    const float* W1l = (const float*)d_in[3];
    const float* b1  = (const float*)d_in[4];
    const float* W1r = (const float*)d_in[5];
    const float* W2l = (const float*)d_in[6];
    const float* b2  = (const float*)d_in[7];
    const float* W2r = (const float*)d_in[8];
    const float* W3l = (const float*)d_in[9];
    const float* b3  = (const float*)d_in[10];
    const float* W3r = (const float*)d_in[11];
    float* out = (float*)d_out;

    const int EB   = (N_EDGES + 255) / 256;
    const int NBK  = (N_NODES + 255) / 256;
    const int AGGB = (N_NODES * 32 + 255) / 256;

    cudaFuncSetAttribute(k_gemm_dual<128, 256, 1, 0, 0>, cudaFuncAttributeMaxDynamicSharedMemorySize, GEMM_SMEM);
    cudaFuncSetAttribute(k_gemm_dual<256, 256, 2, 1, 1>, cudaFuncAttributeMaxDynamicSharedMemorySize, GEMM_SMEM);
    cudaFuncSetAttribute(k_gemm_l3, cudaFuncAttributeMaxDynamicSharedMemorySize, GEMM_SMEM);

    // side stream + events (created per call; capture runs this only a few times)
    cudaStream_t s2;
    cudaStreamCreateWithFlags(&s2, cudaStreamNonBlocking);
    cudaEvent_t e0, e1;
    cudaEventCreateWithFlags(&e0, cudaEventDisableTiming);
    cudaEventCreateWithFlags(&e1, cudaEventDisableTiming);

    // fork: setup (HBM-streaming) on s2, edge chain (atomics) on main
    cudaEventRecord(e0, 0);
    cudaStreamWaitEvent(s2, e0, 0);
    k_setup<<<(SETUP_TOT + 255) / 256, 256, 0, s2>>>(x, batch, W1l, W1r, W2l, W2r, W3l, W3r, out);
    cudaEventRecord(e1, s2);

    k_zero_deg<<<NBK, 256>>>();
    k_count<<<EB, 256>>>(ei);
    k_chunk_sums<<<N_CHUNKS, SCAN_CHUNK>>>();
    k_scan_partials<<<1, 512>>>();
    k_scan_chunks<<<N_CHUNKS, SCAN_CHUNK>>>();
    k_fill<<<EB, 256>>>(ei);

    // join: layer 1 needs both g_fA (setup) and the CSR (fill)
    cudaStreamWaitEvent(0, e1, 0);

    dim3 gm1((N_NODES + 127) / 128, 2);   // N=256
    dim3 gm3((N_NODES + 127) / 128, 2);   // L3: y -> {P3, Q3}

    // layer 1: K=128 -> 256   (in g_fA, out g_fB)
    k_aggregate_f16<2, 0><<<AGGB, 256>>>();
    k_gemm_dual<128, 256, 1, 0, 0><<<gm1, 256, GEMM_SMEM>>>(b1);
    // layer 2: K=256 -> 256   (in g_fB, out g_fA)
    k_aggregate_f16<4, 1><<<AGGB, 256>>>();
    k_gemm_dual<256, 256, 2, 1, 1><<<gm1, 256, GEMM_SMEM>>>(b2);
    // layer 3: P3/Q3 GEMM first, then gather P3 (128-d)
    k_gemm_l3<<<gm3, 256, GEMM_SMEM>>>();
    k_agg_final<<<AGGB, 256>>>(b3);

    // global add pool (out zeroed in k_setup)
    dim3 pg(N_GRAPHS, POOL_SPLIT);
    k_pool_seg<<<pg, 128>>>(out);
}